// round 3
// baseline (speedup 1.0000x reference)
#include <cuda_runtime.h>

typedef unsigned long long ull;

#define NSPECIES 4
#define FDIM 128
#define HDIM 64
#define MAXN 2000000

// ---------------- device scratch (no allocations allowed) ----------------
__device__ int g_meta[8];        // [0..3] species counts, [4..7] scatter cursors
__device__ int g_sorted[MAXN];

// ---------------- per-stage constant weights (one species at a time) ------
__constant__ float c_W1[FDIM * HDIM];   // [k][j] row-major, 32 KB
__constant__ float c_W2[HDIM * HDIM];   // [k][j] row-major, 16 KB
__constant__ float c_b1[HDIM];
__constant__ float c_b2[HDIM];
__constant__ float c_W3[HDIM];
__constant__ float c_b3[1];

// ---------------- packed f32x2 helpers ----------------
__device__ __forceinline__ ull pk(float lo, float hi) {
    ull r;
    asm("mov.b64 %0, {%1, %2};" : "=l"(r)
        : "r"(__float_as_uint(lo)), "r"(__float_as_uint(hi)));
    return r;
}
__device__ __forceinline__ void upk(ull v, float& lo, float& hi) {
    unsigned a, b;
    asm("mov.b64 {%0, %1}, %2;" : "=r"(a), "=r"(b) : "l"(v));
    lo = __uint_as_float(a);
    hi = __uint_as_float(b);
}
__device__ __forceinline__ ull ffma2(ull a, ull b, ull c) {
    ull d;
    asm("fma.rn.f32x2 %0, %1, %2, %3;" : "=l"(d) : "l"(a), "l"(b), "l"(c));
    return d;
}
__device__ __forceinline__ float fast_tanh(float x) {
    // tanh(x) = 1 - 2/(exp(2x)+1); stable at +/-inf.
    float e = __expf(2.0f * x);
    return 1.0f - __fdividef(2.0f, e + 1.0f);
}
__device__ __forceinline__ ull tanh2(ull v) {
    float a, b;
    upk(v, a, b);
    return pk(fast_tanh(a), fast_tanh(b));
}

// ---------------- species dtype detection (per-block, deterministic) ------
// Reference declares int64 but JAX default emits int32. int32 data in [0,3]
// reinterpreted as int64 yields a value outside [0,3] within 128 samples
// with prob 1 - 4^-128.
__device__ __forceinline__ int detect64(const void* sp, int n) {
    const long long* p = (const long long*)sp;
    int m = n / 2 < 128 ? n / 2 : 128;
    int ok = 1;
    #pragma unroll 1
    for (int i = 0; i < m; i++) {
        long long v = p[i];
        if (v < 0 || v > 3) { ok = 0; break; }
    }
    return ok;
}
__device__ __forceinline__ int load_species(const void* sp, int i, int is64) {
    return is64 ? (int)((const long long*)sp)[i] : ((const int*)sp)[i];
}

// ---------------- histogram ----------------
__global__ void hist_kernel(const void* __restrict__ sp, int n) {
    __shared__ int hs[NSPECIES];
    if (threadIdx.x < NSPECIES) hs[threadIdx.x] = 0;
    __syncthreads();
    const int is64 = detect64(sp, n);
    const int stride = gridDim.x * blockDim.x;
    for (int i = blockIdx.x * blockDim.x + threadIdx.x; i < n; i += stride)
        atomicAdd(&hs[load_species(sp, i, is64)], 1);
    __syncthreads();
    if (threadIdx.x < NSPECIES) atomicAdd(&g_meta[threadIdx.x], hs[threadIdx.x]);
}

// ---------------- warp-aggregated scatter (counting-sort pass 2) ----------
__global__ void scatter_kernel(const void* __restrict__ sp, int n) {
    const int is64 = detect64(sp, n);
    // per-block exclusive prefix of counts -> species base offsets
    int offs[NSPECIES];
    {
        int acc = 0;
        #pragma unroll
        for (int s = 0; s < NSPECIES; s++) { offs[s] = acc; acc += g_meta[s]; }
    }
    const int stride = gridDim.x * blockDim.x;
    const int lane = threadIdx.x & 31;
    for (int i = blockIdx.x * blockDim.x + threadIdx.x; i < n; i += stride) {
        int s = load_species(sp, i, is64);
        unsigned act = __activemask();
        unsigned peers = __match_any_sync(act, s);
        int leader = __ffs(peers) - 1;
        int cnt = __popc(peers);
        int base = 0;
        if (lane == leader) base = atomicAdd(&g_meta[NSPECIES + s], cnt);
        base = __shfl_sync(peers, base, leader);
        int pos = offs[s] + base + __popc(peers & ((1u << lane) - 1u));
        g_sorted[pos] = i;
    }
}

// ---------------- main MLP kernel (one species per launch) ----------------
// Column-packed f32x2: h2[jp] = (h_{2jp}, h_{2jp+1}) per atom. Weight operand
// (w_{k,2j}, w_{k,2j+1}) comes straight from __constant__ (constant port; no
// shared-memory crossbar traffic). 2 atoms per thread reuse each weight fetch.
__global__ void __launch_bounds__(256, 1)
mlp_const_kernel(const float* __restrict__ feats,
                 float* __restrict__ out, int s_stage)
{
    // species range from counts (tiny reads, L2-hit)
    int beg = 0;
    #pragma unroll
    for (int s = 0; s < NSPECIES; s++) { if (s < s_stage) beg += g_meta[s]; }
    const int cnt = g_meta[s_stage];
    const int end = beg + cnt;
    const int npairs = (cnt + 1) >> 1;

    const ull* b1p = (const ull*)c_b1;
    const ull* w3p = (const ull*)c_W3;
    const float b3v = c_b3[0];

    const int stride = gridDim.x * blockDim.x;
    for (int p = blockIdx.x * blockDim.x + threadIdx.x; p < npairs; p += stride) {
        const int i0 = beg + 2 * p;
        const bool dup = (i0 + 1 >= end);
        const int i1 = dup ? i0 : i0 + 1;
        const int a0 = g_sorted[i0];
        const int a1 = g_sorted[i1];

        const float4* f0 = (const float4*)(feats + (size_t)a0 * FDIM);
        const float4* f1 = (const float4*)(feats + (size_t)a1 * FDIM);

        // ---- layer 1: h2[a][jp] = (h_{2jp}, h_{2jp+1}) ----
        ull h0[HDIM / 2], h1[HDIM / 2];
        #pragma unroll
        for (int jp = 0; jp < HDIM / 2; jp++) { h0[jp] = b1p[jp]; h1[jp] = b1p[jp]; }

        #pragma unroll 1
        for (int k4 = 0; k4 < FDIM / 4; k4++) {
            const float4 x0 = f0[k4];
            const float4 x1 = f1[k4];
            const float xc0[4] = {x0.x, x0.y, x0.z, x0.w};
            const float xc1[4] = {x1.x, x1.y, x1.z, x1.w};
            #pragma unroll
            for (int c = 0; c < 4; c++) {
                const ull fa = pk(xc0[c], xc0[c]);
                const ull fb = pk(xc1[c], xc1[c]);
                const ull* w = (const ull*)(c_W1 + (k4 * 4 + c) * HDIM);
                #pragma unroll
                for (int jp = 0; jp < HDIM / 2; jp++) {
                    const ull wv = w[jp];
                    h0[jp] = ffma2(fa, wv, h0[jp]);
                    h1[jp] = ffma2(fb, wv, h1[jp]);
                }
            }
        }

        #pragma unroll
        for (int jp = 0; jp < HDIM / 2; jp++) { h0[jp] = tanh2(h0[jp]); h1[jp] = tanh2(h1[jp]); }

        // ---- layer 2 + 3: 16 output cols per jb block ----
        ull e0 = pk(0.f, 0.f), e1 = pk(0.f, 0.f);
        #pragma unroll 1
        for (int jb = 0; jb < 4; jb++) {
            ull a0r[8], a1r[8];
            const ull* b2p = (const ull*)c_b2 + jb * 8;
            #pragma unroll
            for (int ip = 0; ip < 8; ip++) { a0r[ip] = b2p[ip]; a1r[ip] = b2p[ip]; }

            #pragma unroll
            for (int kp = 0; kp < HDIM / 2; kp++) {
                float p0lo, p0hi, p1lo, p1hi;
                upk(h0[kp], p0lo, p0hi);
                upk(h1[kp], p1lo, p1hi);
                const ull d0e = pk(p0lo, p0lo), d0o = pk(p0hi, p0hi);
                const ull d1e = pk(p1lo, p1lo), d1o = pk(p1hi, p1hi);
                const ull* we = (const ull*)(c_W2 + (2 * kp) * HDIM) + jb * 8;
                const ull* wo = (const ull*)(c_W2 + (2 * kp + 1) * HDIM) + jb * 8;
                #pragma unroll
                for (int ip = 0; ip < 8; ip++) {
                    const ull wE = we[ip];
                    const ull wO = wo[ip];
                    a0r[ip] = ffma2(d0e, wE, a0r[ip]);
                    a0r[ip] = ffma2(d0o, wO, a0r[ip]);
                    a1r[ip] = ffma2(d1e, wE, a1r[ip]);
                    a1r[ip] = ffma2(d1o, wO, a1r[ip]);
                }
            }
            #pragma unroll
            for (int ip = 0; ip < 8; ip++) {
                const ull w3v = w3p[jb * 8 + ip];
                e0 = ffma2(tanh2(a0r[ip]), w3v, e0);
                e1 = ffma2(tanh2(a1r[ip]), w3v, e1);
            }
        }

        float lo, hi;
        upk(e0, lo, hi);
        out[a0] = lo + hi + b3v;
        if (!dup) {
            upk(e1, lo, hi);
            out[a1] = lo + hi + b3v;
        }
    }
}

// ---------------- launch ----------------
extern "C" void kernel_launch(void* const* d_in, const int* in_sizes, int n_in,
                              void* d_out, int out_size)
{
    const float* feats   = (const float*)d_in[0];
    const void*  species = d_in[1];
    const float* W1 = (const float*)d_in[2];
    const float* b1 = (const float*)d_in[3];
    const float* W2 = (const float*)d_in[4];
    const float* b2 = (const float*)d_in[5];
    const float* W3 = (const float*)d_in[6];
    const float* b3 = (const float*)d_in[7];
    float* out = (float*)d_out;
    const int n = out_size;

    int dev = 0;
    cudaGetDevice(&dev);
    int nsm = 148;
    cudaDeviceGetAttribute(&nsm, cudaDevAttrMultiProcessorCount, dev);

    // zero counts + cursors (single memset node)
    void* meta_addr = nullptr;
    cudaGetSymbolAddress(&meta_addr, g_meta);
    cudaMemsetAsync(meta_addr, 0, 8 * sizeof(int));

    hist_kernel<<<nsm, 256>>>(species, n);
    scatter_kernel<<<nsm, 256>>>(species, n);

    // 4 sequential per-species stages: stream-ordered D2D copies into the
    // constant bank, then the MLP over that species' sorted range.
    for (int s = 0; s < NSPECIES; s++) {
        cudaMemcpyToSymbolAsync(c_W1, W1 + (size_t)s * FDIM * HDIM,
                                FDIM * HDIM * sizeof(float), 0, cudaMemcpyDeviceToDevice);
        cudaMemcpyToSymbolAsync(c_W2, W2 + (size_t)s * HDIM * HDIM,
                                HDIM * HDIM * sizeof(float), 0, cudaMemcpyDeviceToDevice);
        cudaMemcpyToSymbolAsync(c_b1, b1 + (size_t)s * HDIM,
                                HDIM * sizeof(float), 0, cudaMemcpyDeviceToDevice);
        cudaMemcpyToSymbolAsync(c_b2, b2 + (size_t)s * HDIM,
                                HDIM * sizeof(float), 0, cudaMemcpyDeviceToDevice);
        cudaMemcpyToSymbolAsync(c_W3, W3 + (size_t)s * HDIM,
                                HDIM * sizeof(float), 0, cudaMemcpyDeviceToDevice);
        cudaMemcpyToSymbolAsync(c_b3, b3 + (size_t)s,
                                sizeof(float), 0, cudaMemcpyDeviceToDevice);
        mlp_const_kernel<<<nsm, 256>>>(feats, out, s);
    }
}

// round 5
// speedup vs baseline: 4.4721x; 4.4721x over previous
#include <cuda_runtime.h>
#include <cstdint>

typedef unsigned long long ull;

#define NSPECIES 4
#define FDIM 128
#define HDIM 64
#define MAXN 2000000
#define TM 128          // atoms per tile

// ---------------- device scratch ----------------
__device__ int g_meta[8];     // [0..3] counts, [4..7] scatter cursors
__device__ int g_sorted[MAXN];

// ---------------- packed f32x2 helpers (validated R2) ----------------
__device__ __forceinline__ ull pk(float lo, float hi) {
    ull r;
    asm("mov.b64 %0, {%1, %2};" : "=l"(r)
        : "r"(__float_as_uint(lo)), "r"(__float_as_uint(hi)));
    return r;
}
__device__ __forceinline__ void upk(ull v, float& lo, float& hi) {
    unsigned a, b;
    asm("mov.b64 {%0, %1}, %2;" : "=r"(a), "=r"(b) : "l"(v));
    lo = __uint_as_float(a);
    hi = __uint_as_float(b);
}
__device__ __forceinline__ ull ffma2(ull a, ull b, ull c) {
    ull d;
    asm("fma.rn.f32x2 %0, %1, %2, %3;" : "=l"(d) : "l"(a), "l"(b), "l"(c));
    return d;
}
__device__ __forceinline__ float fast_tanh(float x) {
    // tanh(x) = 1 - 2/(exp(2x)+1); stable at +/-inf.
    float e = __expf(2.0f * x);
    return 1.0f - __fdividef(2.0f, e + 1.0f);
}

// ---------------- species dtype detect + counting sort (validated) -------
__device__ __forceinline__ int detect64(const void* sp, int n) {
    const long long* p = (const long long*)sp;
    int m = n / 2 < 128 ? n / 2 : 128;
    int ok = 1;
    #pragma unroll 1
    for (int i = 0; i < m; i++) { long long v = p[i]; if (v < 0 || v > 3) { ok = 0; break; } }
    return ok;
}
__device__ __forceinline__ int load_sp(const void* sp, int i, int is64) {
    return is64 ? (int)((const long long*)sp)[i] : ((const int*)sp)[i];
}
__global__ void hist_kernel(const void* __restrict__ sp, int n) {
    __shared__ int hs[NSPECIES];
    if (threadIdx.x < NSPECIES) hs[threadIdx.x] = 0;
    __syncthreads();
    const int is64 = detect64(sp, n);
    const int stride = gridDim.x * blockDim.x;
    for (int i = blockIdx.x * blockDim.x + threadIdx.x; i < n; i += stride)
        atomicAdd(&hs[load_sp(sp, i, is64)], 1);
    __syncthreads();
    if (threadIdx.x < NSPECIES) atomicAdd(&g_meta[threadIdx.x], hs[threadIdx.x]);
}
__global__ void scatter_kernel(const void* __restrict__ sp, int n) {
    const int is64 = detect64(sp, n);
    int offs[NSPECIES];
    { int a = 0;
      #pragma unroll
      for (int s = 0; s < NSPECIES; s++) { offs[s] = a; a += g_meta[s]; } }
    const int stride = gridDim.x * blockDim.x;
    const int lane = threadIdx.x & 31;
    for (int i = blockIdx.x * blockDim.x + threadIdx.x; i < n; i += stride) {
        int s = load_sp(sp, i, is64);
        unsigned act = __activemask();
        unsigned peers = __match_any_sync(act, s);
        int leader = __ffs(peers) - 1;
        int cnt = __popc(peers);
        int base = 0;
        if (lane == leader) base = atomicAdd(&g_meta[NSPECIES + s], cnt);
        base = __shfl_sync(peers, base, leader);
        g_sorted[offs[s] + base + __popc(peers & ((1u << lane) - 1u))] = i;
    }
}

// ---------------- SMEM float-offset layout ----------------
#define LDF 132                          // padded row length (atoms dim)
#define OFF_FT 0                         // Ft[k][atom]  : 128 x 132
#define OFF_HT (OFF_FT + FDIM * LDF)     // Ht[j][atom]  : 64 x 132   (16896)
#define OFF_W1 (OFF_HT + HDIM * LDF)     // W1[k][j]     : 128 x 64   (25344)
#define OFF_W2 (OFF_W1 + FDIM * HDIM)    // W2[k][j]     : 64 x 64    (33536)
#define OFF_B1 (OFF_W2 + HDIM * HDIM)    // 64                        (37632)
#define OFF_B2 (OFF_B1 + HDIM)           // 64
#define OFF_W3 (OFF_B2 + HDIM)           // 64
#define OFF_B3 (OFF_W3 + HDIM)           // 1 (+pad)
#define OFF_EP (OFF_B3 + 8)              // Epart[8][128]             (37832)
#define SMEM_FLOATS (OFF_EP + 8 * TM)    // 38856 floats = 155424 B

extern __shared__ float sm[];

__global__ void __launch_bounds__(256, 1)
sgemm_mlp_kernel(const float* __restrict__ feats,
                 const float* __restrict__ W1, const float* __restrict__ b1,
                 const float* __restrict__ W2, const float* __restrict__ b2,
                 const float* __restrict__ W3, const float* __restrict__ b3,
                 float* __restrict__ out)
{
    const int tid = threadIdx.x;
    const int tx = tid & 31;         // atom-chunk index (4 atoms each)
    const int ty = tid >> 5;         // hidden-group index (8 hidden each)
    const int m0 = tx * 4;
    const int n0 = ty * 8;

    // ---- species/tile tables from counts ----
    int beg[NSPECIES], cnt[NSPECIES], tp[NSPECIES + 1];
    { int a = 0, t = 0;
      #pragma unroll
      for (int s = 0; s < NSPECIES; s++) {
          cnt[s] = g_meta[s];
          beg[s] = a; a += cnt[s];
          tp[s] = t; t += (cnt[s] + TM - 1) / TM;
      }
      tp[NSPECIES] = t; }
    const int ntiles = tp[NSPECIES];

    // contiguous tile range per CTA (keeps species changes rare)
    const int tpc = (ntiles + gridDim.x - 1) / gridDim.x;
    const int t0 = blockIdx.x * tpc;
    const int t1 = min(t0 + tpc, ntiles);

    int cur_s = -1;

    for (int t = t0; t < t1; t++) {
        int s = 3;
        if (t < tp[1]) s = 0; else if (t < tp[2]) s = 1; else if (t < tp[3]) s = 2;
        const int start = beg[s] + (t - tp[s]) * TM;
        const int m = min(TM, beg[s] + cnt[s] - start);

        // ---- stage weights on species change ----
        if (s != cur_s) {
            __syncthreads();   // previous tile done reading old weights
            for (int i = tid; i < FDIM * HDIM; i += 256)
                sm[OFF_W1 + i] = W1[s * FDIM * HDIM + i];
            for (int i = tid; i < HDIM * HDIM; i += 256)
                sm[OFF_W2 + i] = W2[s * HDIM * HDIM + i];
            if (tid < HDIM) {
                sm[OFF_B1 + tid] = b1[s * HDIM + tid];
                sm[OFF_B2 + tid] = b2[s * HDIM + tid];
                sm[OFF_W3 + tid] = W3[s * HDIM + tid];
            }
            if (tid == 0) sm[OFF_B3] = b3[s];
            cur_s = s;
            __syncthreads();
        } else {
            __syncthreads();   // previous tile's output-reduce done before Ft overwrite
        }

        // ---- gather feature tile, transposed: Ft[k][row] ----
        {
            const int row = tid & 127;
            const int half = tid >> 7;          // 0/1: k 0-63 / 64-127
            const int ridx = row < m ? row : m - 1;
            const int atom = g_sorted[start + ridx];
            const float4* src = (const float4*)(feats + (size_t)atom * FDIM + half * 64);
            #pragma unroll 4
            for (int q = 0; q < 16; q++) {
                float4 v = src[q];
                int k = half * 64 + q * 4;
                sm[OFF_FT + (k + 0) * LDF + row] = v.x;
                sm[OFF_FT + (k + 1) * LDF + row] = v.y;
                sm[OFF_FT + (k + 2) * LDF + row] = v.z;
                sm[OFF_FT + (k + 3) * LDF + row] = v.w;
            }
        }
        __syncthreads();

        // ---- layer 1: acc[4 atoms][4 hidden-pairs] ----
        ull acc[4][4];
        {
            const ull* b1p = (const ull*)(sm + OFF_B1 + n0);
            #pragma unroll
            for (int a = 0; a < 4; a++)
                #pragma unroll
                for (int np = 0; np < 4; np++) acc[a][np] = b1p[np];

            #pragma unroll 4
            for (int k = 0; k < FDIM; k++) {
                const float4 av = *(const float4*)(sm + OFF_FT + k * LDF + m0);
                const ulonglong2* wp = (const ulonglong2*)(sm + OFF_W1 + k * HDIM + n0);
                const ulonglong2 w01 = wp[0];
                const ulonglong2 w23 = wp[1];
                const ull fa0 = pk(av.x, av.x);
                const ull fa1 = pk(av.y, av.y);
                const ull fa2 = pk(av.z, av.z);
                const ull fa3 = pk(av.w, av.w);
                acc[0][0] = ffma2(fa0, w01.x, acc[0][0]);
                acc[0][1] = ffma2(fa0, w01.y, acc[0][1]);
                acc[0][2] = ffma2(fa0, w23.x, acc[0][2]);
                acc[0][3] = ffma2(fa0, w23.y, acc[0][3]);
                acc[1][0] = ffma2(fa1, w01.x, acc[1][0]);
                acc[1][1] = ffma2(fa1, w01.y, acc[1][1]);
                acc[1][2] = ffma2(fa1, w23.x, acc[1][2]);
                acc[1][3] = ffma2(fa1, w23.y, acc[1][3]);
                acc[2][0] = ffma2(fa2, w01.x, acc[2][0]);
                acc[2][1] = ffma2(fa2, w01.y, acc[2][1]);
                acc[2][2] = ffma2(fa2, w23.x, acc[2][2]);
                acc[2][3] = ffma2(fa2, w23.y, acc[2][3]);
                acc[3][0] = ffma2(fa3, w01.x, acc[3][0]);
                acc[3][1] = ffma2(fa3, w01.y, acc[3][1]);
                acc[3][2] = ffma2(fa3, w23.x, acc[3][2]);
                acc[3][3] = ffma2(fa3, w23.y, acc[3][3]);
            }
        }

        // ---- tanh, store Ht[j][atom] (atoms m0..m0+3 are this thread's) ----
        #pragma unroll
        for (int a = 0; a < 4; a++) {
            #pragma unroll
            for (int np = 0; np < 4; np++) {
                float v0, v1;
                upk(acc[a][np], v0, v1);
                sm[OFF_HT + (n0 + 2 * np + 0) * LDF + m0 + a] = fast_tanh(v0);
                sm[OFF_HT + (n0 + 2 * np + 1) * LDF + m0 + a] = fast_tanh(v1);
            }
        }
        __syncthreads();

        // ---- layer 2 ----
        {
            const ull* b2p = (const ull*)(sm + OFF_B2 + n0);
            #pragma unroll
            for (int a = 0; a < 4; a++)
                #pragma unroll
                for (int np = 0; np < 4; np++) acc[a][np] = b2p[np];

            #pragma unroll 4
            for (int k = 0; k < HDIM; k++) {
                const float4 av = *(const float4*)(sm + OFF_HT + k * LDF + m0);
                const ulonglong2* wp = (const ulonglong2*)(sm + OFF_W2 + k * HDIM + n0);
                const ulonglong2 w01 = wp[0];
                const ulonglong2 w23 = wp[1];
                const ull fa0 = pk(av.x, av.x);
                const ull fa1 = pk(av.y, av.y);
                const ull fa2 = pk(av.z, av.z);
                const ull fa3 = pk(av.w, av.w);
                acc[0][0] = ffma2(fa0, w01.x, acc[0][0]);
                acc[0][1] = ffma2(fa0, w01.y, acc[0][1]);
                acc[0][2] = ffma2(fa0, w23.x, acc[0][2]);
                acc[0][3] = ffma2(fa0, w23.y, acc[0][3]);
                acc[1][0] = ffma2(fa1, w01.x, acc[1][0]);
                acc[1][1] = ffma2(fa1, w01.y, acc[1][1]);
                acc[1][2] = ffma2(fa1, w23.x, acc[1][2]);
                acc[1][3] = ffma2(fa1, w23.y, acc[1][3]);
                acc[2][0] = ffma2(fa2, w01.x, acc[2][0]);
                acc[2][1] = ffma2(fa2, w01.y, acc[2][1]);
                acc[2][2] = ffma2(fa2, w23.x, acc[2][2]);
                acc[2][3] = ffma2(fa2, w23.y, acc[2][3]);
                acc[3][0] = ffma2(fa3, w01.x, acc[3][0]);
                acc[3][1] = ffma2(fa3, w01.y, acc[3][1]);
                acc[3][2] = ffma2(fa3, w23.x, acc[3][2]);
                acc[3][3] = ffma2(fa3, w23.y, acc[3][3]);
            }
        }

        // ---- tanh, dot with W3 slice, partial energies ----
        {
            const ull* w3p = (const ull*)(sm + OFF_W3 + n0);
            const ull w3r[4] = { w3p[0], w3p[1], w3p[2], w3p[3] };
            #pragma unroll
            for (int a = 0; a < 4; a++) {
                ull e2 = pk(0.0f, 0.0f);
                #pragma unroll
                for (int np = 0; np < 4; np++) {
                    float v0, v1;
                    upk(acc[a][np], v0, v1);
                    e2 = ffma2(pk(fast_tanh(v0), fast_tanh(v1)), w3r[np], e2);
                }
                float e0, e1;
                upk(e2, e0, e1);
                sm[OFF_EP + ty * TM + m0 + a] = e0 + e1;
            }
        }
        __syncthreads();

        // ---- reduce 8 partials per atom, write out ----
        if (tid < TM && tid < m) {
            float e = sm[OFF_B3];
            #pragma unroll
            for (int g = 0; g < 8; g++) e += sm[OFF_EP + g * TM + tid];
            out[g_sorted[start + tid]] = e;
        }
        // next iteration begins with __syncthreads before Ft overwrite
    }
}

// ---------------- launch ----------------
extern "C" void kernel_launch(void* const* d_in, const int* in_sizes, int n_in,
                              void* d_out, int out_size)
{
    const float* feats   = (const float*)d_in[0];
    const void*  species = d_in[1];
    const float* W1 = (const float*)d_in[2];
    const float* b1 = (const float*)d_in[3];
    const float* W2 = (const float*)d_in[4];
    const float* b2 = (const float*)d_in[5];
    const float* W3 = (const float*)d_in[6];
    const float* b3 = (const float*)d_in[7];
    float* out = (float*)d_out;
    const int n = out_size;

    int dev = 0;
    cudaGetDevice(&dev);
    int nsm = 148;
    cudaDeviceGetAttribute(&nsm, cudaDevAttrMultiProcessorCount, dev);

    void* meta_addr = nullptr;
    cudaGetSymbolAddress(&meta_addr, g_meta);
    cudaMemsetAsync(meta_addr, 0, 8 * sizeof(int));

    hist_kernel<<<nsm, 256>>>(species, n);
    scatter_kernel<<<nsm, 256>>>(species, n);

    const size_t smem_bytes = SMEM_FLOATS * sizeof(float);
    cudaFuncSetAttribute(sgemm_mlp_kernel,
                         cudaFuncAttributeMaxDynamicSharedMemorySize,
                         (int)smem_bytes);
    sgemm_mlp_kernel<<<nsm, 256, smem_bytes>>>(feats, W1, b1, W2, b2, W3, b3, out);
}

// round 6
// speedup vs baseline: 4.7012x; 1.0512x over previous
#include <cuda_runtime.h>
#include <cstdint>

typedef unsigned long long ull;

#define NSPECIES 4
#define FDIM 128
#define HDIM 64
#define MAXN 2000000
#define TM 128
#define LDF 132

// ---------------- device scratch ----------------
__device__ int g_meta[8];     // [0..3] counts, [4..7] scatter cursors
__device__ int g_sorted[MAXN];

// ---------------- packed f32x2 helpers (validated) ----------------
__device__ __forceinline__ ull pk(float lo, float hi) {
    ull r;
    asm("mov.b64 %0, {%1, %2};" : "=l"(r)
        : "r"(__float_as_uint(lo)), "r"(__float_as_uint(hi)));
    return r;
}
__device__ __forceinline__ void upk(ull v, float& lo, float& hi) {
    unsigned a, b;
    asm("mov.b64 {%0, %1}, %2;" : "=r"(a), "=r"(b) : "l"(v));
    lo = __uint_as_float(a);
    hi = __uint_as_float(b);
}
__device__ __forceinline__ ull ffma2(ull a, ull b, ull c) {
    ull d;
    asm("fma.rn.f32x2 %0, %1, %2, %3;" : "=l"(d) : "l"(a), "l"(b), "l"(c));
    return d;
}
__device__ __forceinline__ float fast_tanh(float x) {
    // tanh(x) = 1 - 2/(exp(2x)+1); stable at +/-inf.
    float e = __expf(2.0f * x);
    return 1.0f - __fdividef(2.0f, e + 1.0f);
}

// ---------------- species dtype detect + counting sort (validated) -------
__device__ __forceinline__ int detect64(const void* sp, int n) {
    const long long* p = (const long long*)sp;
    int m = n / 2 < 128 ? n / 2 : 128;
    int ok = 1;
    #pragma unroll 1
    for (int i = 0; i < m; i++) { long long v = p[i]; if (v < 0 || v > 3) { ok = 0; break; } }
    return ok;
}
__device__ __forceinline__ int load_sp(const void* sp, int i, int is64) {
    return is64 ? (int)((const long long*)sp)[i] : ((const int*)sp)[i];
}
__global__ void hist_kernel(const void* __restrict__ sp, int n) {
    __shared__ int hs[NSPECIES];
    if (threadIdx.x < NSPECIES) hs[threadIdx.x] = 0;
    __syncthreads();
    const int is64 = detect64(sp, n);
    const int stride = gridDim.x * blockDim.x;
    for (int i = blockIdx.x * blockDim.x + threadIdx.x; i < n; i += stride)
        atomicAdd(&hs[load_sp(sp, i, is64)], 1);
    __syncthreads();
    if (threadIdx.x < NSPECIES) atomicAdd(&g_meta[threadIdx.x], hs[threadIdx.x]);
}
__global__ void scatter_kernel(const void* __restrict__ sp, int n) {
    const int is64 = detect64(sp, n);
    int offs[NSPECIES];
    { int a = 0;
      #pragma unroll
      for (int s = 0; s < NSPECIES; s++) { offs[s] = a; a += g_meta[s]; } }
    const int stride = gridDim.x * blockDim.x;
    const int lane = threadIdx.x & 31;
    for (int i = blockIdx.x * blockDim.x + threadIdx.x; i < n; i += stride) {
        int s = load_sp(sp, i, is64);
        unsigned act = __activemask();
        unsigned peers = __match_any_sync(act, s);
        int leader = __ffs(peers) - 1;
        int cnt = __popc(peers);
        int base = 0;
        if (lane == leader) base = atomicAdd(&g_meta[NSPECIES + s], cnt);
        base = __shfl_sync(peers, base, leader);
        g_sorted[offs[s] + base + __popc(peers & ((1u << lane) - 1u))] = i;
    }
}

// ---------------- SMEM float-offset layout ----------------
// Two feature tiles (one per 128-thread group); Ht overlays Ft rows 0..63.
#define OFF_FT0 0
#define OFF_FT1 (OFF_FT0 + FDIM * LDF)       // 16896
#define OFF_W1  (OFF_FT1 + FDIM * LDF)       // 33792 : W1[k][j] 128x64
#define OFF_W2  (OFF_W1 + FDIM * HDIM)       // 41984 : W2[k][j] 64x64
#define OFF_B1  (OFF_W2 + HDIM * HDIM)       // 46080
#define OFF_B2  (OFF_B1 + HDIM)
#define OFF_W3  (OFF_B2 + HDIM)
#define OFF_B3  (OFF_W3 + HDIM)              // 46272 (+pad)
#define OFF_EP  (OFF_B3 + 8)                 // Epart[2][8][128]
#define SMEM_FLOATS (OFF_EP + 2 * 8 * TM)    // 48328 floats = 193312 B

extern __shared__ float sm[];

#define GBAR(id) asm volatile("bar.sync %0, 128;" :: "r"(id) : "memory")

__global__ void __launch_bounds__(256, 1)
sgemm2_mlp_kernel(const float* __restrict__ feats,
                  const float* __restrict__ W1, const float* __restrict__ b1,
                  const float* __restrict__ W2, const float* __restrict__ b2,
                  const float* __restrict__ W3, const float* __restrict__ b3,
                  float* __restrict__ out)
{
    const int tid = threadIdx.x;
    const int g   = tid >> 7;          // group 0/1
    const int gid = tid & 127;
    const int tx  = gid & 15;          // 16 atom-chunks of 8
    const int ty  = gid >> 4;          // 8 hidden-groups of 8
    const int m0  = tx * 8;
    const int n0  = ty * 8;
    const int FT  = g ? OFF_FT1 : OFF_FT0;
    const int EP  = OFF_EP + g * 8 * TM;
    const int barid = 1 + g;

    // ---- species / tile-pair tables ----
    int beg[NSPECIES], cnt[NSPECIES], tiles[NSPECIES], pp[NSPECIES + 1];
    { int a = 0, p = 0;
      #pragma unroll
      for (int s = 0; s < NSPECIES; s++) {
          cnt[s] = g_meta[s];
          beg[s] = a; a += cnt[s];
          tiles[s] = (cnt[s] + TM - 1) / TM;
          pp[s] = p; p += (tiles[s] + 1) >> 1;     // tile PAIRS per species
      }
      pp[NSPECIES] = p; }
    const int npairs = pp[NSPECIES];

    const int ppc = (npairs + gridDim.x - 1) / gridDim.x;
    const int p0 = blockIdx.x * ppc;
    const int p1 = min(p0 + ppc, npairs);

    int cur_s = -1;
    for (int p = p0; p < p1; p++) {
        int s = 3;
        if (p < pp[1]) s = 0; else if (p < pp[2]) s = 1; else if (p < pp[3]) s = 2;

        // ---- weight staging on species change (whole CTA) ----
        if (s != cur_s) {
            __syncthreads();           // both groups done with old weights
            for (int i = tid; i < FDIM * HDIM; i += 256)
                sm[OFF_W1 + i] = W1[s * FDIM * HDIM + i];
            for (int i = tid; i < HDIM * HDIM; i += 256)
                sm[OFF_W2 + i] = W2[s * HDIM * HDIM + i];
            if (tid < HDIM) {
                sm[OFF_B1 + tid] = b1[s * HDIM + tid];
                sm[OFF_B2 + tid] = b2[s * HDIM + tid];
                sm[OFF_W3 + tid] = W3[s * HDIM + tid];
            }
            if (tid == 0) sm[OFF_B3] = b3[s];
            cur_s = s;
            __syncthreads();
        }

        const int tile = (p - pp[s]) * 2 + g;
        if (tile >= tiles[s]) continue;            // odd-tile: this group idles
        const int start = beg[s] + tile * TM;
        const int m = min(TM, cnt[s] - tile * TM);

        // ---- gather feature tile, transposed Ft[k][row] (group-local) ----
        {
            const int ridx = gid < m ? gid : m - 1;
            const int atom = g_sorted[start + ridx];
            const float4* src = (const float4*)(feats + (size_t)atom * FDIM);
            #pragma unroll 8
            for (int q = 0; q < 32; q++) {
                float4 v = src[q];
                const int k = q * 4;
                sm[FT + (k + 0) * LDF + gid] = v.x;
                sm[FT + (k + 1) * LDF + gid] = v.y;
                sm[FT + (k + 2) * LDF + gid] = v.z;
                sm[FT + (k + 3) * LDF + gid] = v.w;
            }
        }
        GBAR(barid);

        // ---- layer 1: acc[8 atoms][4 hidden-pairs] ----
        ull acc[8][4];
        {
            const ull* b1p = (const ull*)(sm + OFF_B1 + n0);
            const ull bi[4] = { b1p[0], b1p[1], b1p[2], b1p[3] };
            #pragma unroll
            for (int a = 0; a < 8; a++)
                #pragma unroll
                for (int np = 0; np < 4; np++) acc[a][np] = bi[np];

            #pragma unroll 4
            for (int k = 0; k < FDIM; k++) {
                const float4 a0 = *(const float4*)(sm + FT + k * LDF + m0);
                const float4 a1 = *(const float4*)(sm + FT + k * LDF + m0 + 4);
                const ulonglong2 w01 = *(const ulonglong2*)(sm + OFF_W1 + k * HDIM + n0);
                const ulonglong2 w23 = *(const ulonglong2*)(sm + OFF_W1 + k * HDIM + n0 + 4);
                const ull f[8] = { pk(a0.x, a0.x), pk(a0.y, a0.y), pk(a0.z, a0.z), pk(a0.w, a0.w),
                                   pk(a1.x, a1.x), pk(a1.y, a1.y), pk(a1.z, a1.z), pk(a1.w, a1.w) };
                const ull w[4] = { w01.x, w01.y, w23.x, w23.y };
                #pragma unroll
                for (int a = 0; a < 8; a++)
                    #pragma unroll
                    for (int np = 0; np < 4; np++)
                        acc[a][np] = ffma2(f[a], w[np], acc[a][np]);
            }
        }
        GBAR(barid);                    // all reads of Ft done before Ht overlay

        // ---- tanh -> Ht[j][atom] (overlays Ft rows 0..63) ----
        #pragma unroll
        for (int np = 0; np < 4; np++) {
            float lo[8], hi[8];
            #pragma unroll
            for (int a = 0; a < 8; a++) {
                float x, y;
                upk(acc[a][np], x, y);
                lo[a] = fast_tanh(x);
                hi[a] = fast_tanh(y);
            }
            *(float4*)(sm + FT + (n0 + 2 * np) * LDF + m0)     = make_float4(lo[0], lo[1], lo[2], lo[3]);
            *(float4*)(sm + FT + (n0 + 2 * np) * LDF + m0 + 4) = make_float4(lo[4], lo[5], lo[6], lo[7]);
            *(float4*)(sm + FT + (n0 + 2 * np + 1) * LDF + m0)     = make_float4(hi[0], hi[1], hi[2], hi[3]);
            *(float4*)(sm + FT + (n0 + 2 * np + 1) * LDF + m0 + 4) = make_float4(hi[4], hi[5], hi[6], hi[7]);
        }
        GBAR(barid);

        // ---- layer 2 ----
        {
            const ull* b2p = (const ull*)(sm + OFF_B2 + n0);
            const ull bi[4] = { b2p[0], b2p[1], b2p[2], b2p[3] };
            #pragma unroll
            for (int a = 0; a < 8; a++)
                #pragma unroll
                for (int np = 0; np < 4; np++) acc[a][np] = bi[np];

            #pragma unroll 4
            for (int k = 0; k < HDIM; k++) {
                const float4 a0 = *(const float4*)(sm + FT + k * LDF + m0);
                const float4 a1 = *(const float4*)(sm + FT + k * LDF + m0 + 4);
                const ulonglong2 w01 = *(const ulonglong2*)(sm + OFF_W2 + k * HDIM + n0);
                const ulonglong2 w23 = *(const ulonglong2*)(sm + OFF_W2 + k * HDIM + n0 + 4);
                const ull f[8] = { pk(a0.x, a0.x), pk(a0.y, a0.y), pk(a0.z, a0.z), pk(a0.w, a0.w),
                                   pk(a1.x, a1.x), pk(a1.y, a1.y), pk(a1.z, a1.z), pk(a1.w, a1.w) };
                const ull w[4] = { w01.x, w01.y, w23.x, w23.y };
                #pragma unroll
                for (int a = 0; a < 8; a++)
                    #pragma unroll
                    for (int np = 0; np < 4; np++)
                        acc[a][np] = ffma2(f[a], w[np], acc[a][np]);
            }
        }

        // ---- tanh, dot W3 slice, partial energies ----
        {
            const ull* w3p = (const ull*)(sm + OFF_W3 + n0);
            const ull w3r[4] = { w3p[0], w3p[1], w3p[2], w3p[3] };
            #pragma unroll
            for (int a = 0; a < 8; a++) {
                ull e2 = pk(0.0f, 0.0f);
                #pragma unroll
                for (int np = 0; np < 4; np++) {
                    float x, y;
                    upk(acc[a][np], x, y);
                    e2 = ffma2(pk(fast_tanh(x), fast_tanh(y)), w3r[np], e2);
                }
                float e0, e1;
                upk(e2, e0, e1);
                sm[EP + ty * TM + m0 + a] = e0 + e1;
            }
        }
        GBAR(barid);

        // ---- reduce 8 partials per atom ----
        if (gid < m) {
            float e = sm[OFF_B3];
            #pragma unroll
            for (int t = 0; t < 8; t++) e += sm[EP + t * TM + gid];
            out[g_sorted[start + gid]] = e;
        }
        // next gather overwrites Ft only after this group's threads all pass GBAR(1)
    }
}

// ---------------- launch ----------------
extern "C" void kernel_launch(void* const* d_in, const int* in_sizes, int n_in,
                              void* d_out, int out_size)
{
    const float* feats   = (const float*)d_in[0];
    const void*  species = d_in[1];
    const float* W1 = (const float*)d_in[2];
    const float* b1 = (const float*)d_in[3];
    const float* W2 = (const float*)d_in[4];
    const float* b2 = (const float*)d_in[5];
    const float* W3 = (const float*)d_in[6];
    const float* b3 = (const float*)d_in[7];
    float* out = (float*)d_out;
    const int n = out_size;

    int dev = 0;
    cudaGetDevice(&dev);
    int nsm = 148;
    cudaDeviceGetAttribute(&nsm, cudaDevAttrMultiProcessorCount, dev);

    void* meta_addr = nullptr;
    cudaGetSymbolAddress(&meta_addr, g_meta);
    cudaMemsetAsync(meta_addr, 0, 8 * sizeof(int));

    hist_kernel<<<nsm, 256>>>(species, n);
    scatter_kernel<<<nsm, 256>>>(species, n);

    const size_t smem_bytes = SMEM_FLOATS * sizeof(float);
    cudaFuncSetAttribute(sgemm2_mlp_kernel,
                         cudaFuncAttributeMaxDynamicSharedMemorySize,
                         (int)smem_bytes);
    sgemm2_mlp_kernel<<<nsm, 256, smem_bytes>>>(feats, W1, b1, W2, b2, W3, b3, out);
}